// round 2
// baseline (speedup 1.0000x reference)
#include <cuda_runtime.h>
#include <cstdint>

#define D 64
#define MAX_NODES 100000

// Scratch: h_new accumulator (25.6 MB), float4 for 16B alignment (red.v4 target).
__device__ float4 g_hnew4[MAX_NODES * (D / 4)];
// Index-dtype flag: 1 if src/dst buffers are int32, 0 if int64.
__device__ int g_is32;

// ---------------------------------------------------------------------------
// f32x2 helpers (Blackwell packed fp32 — ptxas will not auto-fuse these)
// ---------------------------------------------------------------------------
__device__ __forceinline__ unsigned long long fma2(unsigned long long a,
                                                   unsigned long long b,
                                                   unsigned long long c) {
    unsigned long long d;
    asm("fma.rn.f32x2 %0, %1, %2, %3;" : "=l"(d) : "l"(a), "l"(b), "l"(c));
    return d;
}
__device__ __forceinline__ unsigned long long pack2(float a, float b) {
    unsigned long long r;
    asm("mov.b64 %0, {%1, %2};" : "=l"(r) : "f"(a), "f"(b));
    return r;
}
__device__ __forceinline__ float hsum2(unsigned long long a) {
    float lo, hi;
    asm("mov.b64 {%0, %1}, %2;" : "=f"(lo), "=f"(hi) : "l"(a));
    return lo + hi;
}

__device__ __forceinline__ float sigmoidf_fast(float x) {
    return __fdividef(1.0f, 1.0f + __expf(-x));
}
// tanh via exp, overflow-safe at both ends: tanh(x) = 1 - 2/(e^{2x}+1)
__device__ __forceinline__ float tanhf_fast(float x) {
    return 1.0f - __fdividef(2.0f, __expf(2.0f * x) + 1.0f);
}

// ---------------------------------------------------------------------------
// Kernel 0: detect whether src/dst are int32 or int64.
// int64 values are in [0, 1e5) -> high 32 bits always zero.
// int32 data read as u64 pairs has random node ids in the high word.
// ---------------------------------------------------------------------------
__global__ void detect_kernel(const unsigned long long* __restrict__ src,
                              const unsigned long long* __restrict__ dst) {
    if (threadIdx.x == 0 && blockIdx.x == 0) {
        unsigned long long acc = 0;
#pragma unroll
        for (int i = 0; i < 8; i++) acc |= (src[i] >> 32) | (dst[i] >> 32);
        g_is32 = (acc != 0ULL) ? 1 : 0;
    }
}

// ---------------------------------------------------------------------------
// Kernel 1: zero the accumulator
// ---------------------------------------------------------------------------
__global__ void zero_kernel(int n4) {
    int i = blockIdx.x * blockDim.x + threadIdx.x;
    if (i < n4) g_hnew4[i] = make_float4(0.f, 0.f, 0.f, 0.f);
}

// ---------------------------------------------------------------------------
// Kernel 2: edge scatter.  16 threads per edge, one float4 each.
// Gather h[src] row (256B, coalesced), scale by w_e, vector-reduce into
// g_hnew4[dst] with red.global.add.v4.f32 (L2-resident, no return value).
// ---------------------------------------------------------------------------
__global__ void scatter_kernel(const float4* __restrict__ h4,
                               const float* __restrict__ ew,
                               const void* __restrict__ srcp,
                               const void* __restrict__ dstp,
                               int E) {
    int gid = blockIdx.x * blockDim.x + threadIdx.x;
    int e = gid >> 4;
    int p = gid & 15;
    if (e >= E) return;

    int s, d;
    if (g_is32) {
        s = ((const int*)srcp)[e];
        d = ((const int*)dstp)[e];
    } else {
        s = (int)((const long long*)srcp)[e];
        d = (int)((const long long*)dstp)[e];
    }
    float w = ew[e];
    float4 v = __ldg(&h4[s * 16 + p]);
    v.x *= w; v.y *= w; v.z *= w; v.w *= w;

    float4* ptr = &g_hnew4[d * 16 + p];
    unsigned long long gptr = __cvta_generic_to_global((void*)ptr);
    asm volatile("red.global.add.v4.f32 [%0], {%1, %2, %3, %4};"
                 :: "l"(gptr), "f"(v.x), "f"(v.y), "f"(v.z), "f"(v.w)
                 : "memory");
}

// ---------------------------------------------------------------------------
// Kernel 3: fused GEMM (x@W_ih^T, h@W_hh^T) + biases + GRU gates.
// One node per thread; x,h rows cached in registers as f32x2 pairs;
// W_ih|W_hh (98304 B) broadcast from dynamic SMEM; 6 independent f32x2
// accumulator chains per output column j.
// NOTE: reads g_hnew4 DIRECTLY as a device symbol (host-side &g_hnew4 is the
// shadow object and, under GB300 ATS, silently reads host zeros).
// ---------------------------------------------------------------------------
__global__ void __launch_bounds__(128, 1)
gru_kernel(const float* __restrict__ h,
           const float4* __restrict__ Wih4,
           const float4* __restrict__ Whh4,
           const float* __restrict__ bih,
           const float* __restrict__ bhh,
           float* __restrict__ out,
           int N) {
    extern __shared__ __align__(16) float sW[];  // 24576 floats: W_ih then W_hh
    float4* sW4 = (float4*)sW;
    for (int i = threadIdx.x; i < 6144; i += blockDim.x)
        sW4[i] = (i < 3072) ? __ldg(&Wih4[i]) : __ldg(&Whh4[i - 3072]);
    __syncthreads();

    int node = blockIdx.x * blockDim.x + threadIdx.x;
    if (node >= N) return;

    // Cache this node's x (= h_new row) and h row in registers (f32x2 packed)
    unsigned long long xr[32], hr[32];
    const float4* xp = &g_hnew4[node * 16];
    const float4* hp = (const float4*)(h + (size_t)node * D);
#pragma unroll
    for (int i = 0; i < 16; i++) {
        float4 v = xp[i];
        xr[2 * i]     = pack2(v.x, v.y);
        xr[2 * i + 1] = pack2(v.z, v.w);
        float4 u = __ldg(&hp[i]);
        hr[2 * i]     = pack2(u.x, u.y);
        hr[2 * i + 1] = pack2(u.z, u.w);
    }

    const float* sWih = sW;
    const float* sWhh = sW + 12288;

    for (int j = 0; j < D; j++) {
        const ulonglong2* wir = (const ulonglong2*)(sWih + j * D);
        const ulonglong2* wiz = (const ulonglong2*)(sWih + (D + j) * D);
        const ulonglong2* win = (const ulonglong2*)(sWih + (2 * D + j) * D);
        const ulonglong2* whr = (const ulonglong2*)(sWhh + j * D);
        const ulonglong2* whz = (const ulonglong2*)(sWhh + (D + j) * D);
        const ulonglong2* whn = (const ulonglong2*)(sWhh + (2 * D + j) * D);

        unsigned long long air = 0, aiz = 0, ain = 0;
        unsigned long long ahr = 0, ahz = 0, ahn = 0;
#pragma unroll
        for (int k = 0; k < 16; k++) {
            ulonglong2 w;
            w = wir[k]; air = fma2(w.x, xr[2 * k], air); air = fma2(w.y, xr[2 * k + 1], air);
            w = wiz[k]; aiz = fma2(w.x, xr[2 * k], aiz); aiz = fma2(w.y, xr[2 * k + 1], aiz);
            w = win[k]; ain = fma2(w.x, xr[2 * k], ain); ain = fma2(w.y, xr[2 * k + 1], ain);
            w = whr[k]; ahr = fma2(w.x, hr[2 * k], ahr); ahr = fma2(w.y, hr[2 * k + 1], ahr);
            w = whz[k]; ahz = fma2(w.x, hr[2 * k], ahz); ahz = fma2(w.y, hr[2 * k + 1], ahz);
            w = whn[k]; ahn = fma2(w.x, hr[2 * k], ahn); ahn = fma2(w.y, hr[2 * k + 1], ahn);
        }
        float i_r = hsum2(air) + __ldg(&bih[j]);
        float h_r = hsum2(ahr) + __ldg(&bhh[j]);
        float i_z = hsum2(aiz) + __ldg(&bih[D + j]);
        float h_z = hsum2(ahz) + __ldg(&bhh[D + j]);
        float i_n = hsum2(ain) + __ldg(&bih[2 * D + j]);
        float h_n = hsum2(ahn) + __ldg(&bhh[2 * D + j]);

        float r = sigmoidf_fast(i_r + h_r);
        float z = sigmoidf_fast(i_z + h_z);
        float nn = tanhf_fast(i_n + r * h_n);
        float hj = __ldg(&h[(size_t)node * D + j]);
        out[(size_t)node * D + j] = (1.0f - z) * nn + z * hj;
    }
}

// ---------------------------------------------------------------------------
// Launch
// ---------------------------------------------------------------------------
extern "C" void kernel_launch(void* const* d_in, const int* in_sizes, int n_in,
                              void* d_out, int out_size) {
    const float* h     = (const float*)d_in[0];
    const float* ew    = (const float*)d_in[1];
    const float4* Wih4 = (const float4*)d_in[2];
    const float4* Whh4 = (const float4*)d_in[3];
    const float* bih   = (const float*)d_in[4];
    const float* bhh   = (const float*)d_in[5];
    const void* srcp   = d_in[6];
    const void* dstp   = d_in[7];
    float* out         = (float*)d_out;

    int E = in_sizes[1];          // edge_weights element count == E (dtype-safe)
    int N = in_sizes[0] / D;      // nodes

    detect_kernel<<<1, 32>>>((const unsigned long long*)srcp,
                             (const unsigned long long*)dstp);

    int n4 = N * (D / 4);
    zero_kernel<<<(n4 + 255) / 256, 256>>>(n4);

    long long total = (long long)E * 16;
    int sblocks = (int)((total + 255) / 256);
    scatter_kernel<<<sblocks, 256>>>((const float4*)h, ew, srcp, dstp, E);

    static_assert(sizeof(float) * 24576 == 98304, "");
    cudaFuncSetAttribute(gru_kernel, cudaFuncAttributeMaxDynamicSharedMemorySize,
                         98304);
    gru_kernel<<<(N + 127) / 128, 128, 98304>>>(
        h, Wih4, Whh4, bih, bhh, out, N);
}

// round 4
// speedup vs baseline: 1.7967x; 1.7967x over previous
#include <cuda_runtime.h>
#include <cstdint>

#define D 64
#define NMAX 100000

// ---------------------------------------------------------------------------
// Device scratch
// ---------------------------------------------------------------------------
__device__ float4  g_hnew4[NMAX * (D / 4)];   // h_new accumulator (25.6 MB)
__device__ uint8_t g_Bimg[139264];            // bf16 hi (69632) + lo (69632) weight image
__device__ float   g_biasf[256];              // fused biases, col' = j*4+gate order
__device__ int     g_is32;                    // src/dst dtype flag

// SMEM map for the GEMM kernel
#define STRIDE_A 272            // 128 k * 2B padded to 17*16B (ldmatrix conflict-free)
#define A_HALF   34816          // 128 rows * 272
#define B_HALF   69632          // 256 rows * 272
#define SM_BIAS  0
#define SM_A     1024
#define SM_B     (SM_A + 2 * A_HALF)          // 70656
#define SM_TOT   (SM_B + 2 * B_HALF)          // 209920

// ---------------------------------------------------------------------------
// Helpers
// ---------------------------------------------------------------------------
__device__ __forceinline__ uint32_t smem_u32(const void* p) {
    uint32_t a;
    asm("{ .reg .u64 t; cvta.to.shared.u64 t, %1; cvt.u32.u64 %0, t; }"
        : "=r"(a) : "l"(p));
    return a;
}
__device__ __forceinline__ uint32_t cvtbf2(float hi, float lo) {
    uint32_t d;
    asm("cvt.rn.bf16x2.f32 %0, %1, %2;" : "=r"(d) : "f"(hi), "f"(lo));
    return d;
}
__device__ __forceinline__ float bflo_f(uint32_t p) { return __uint_as_float(p << 16); }
__device__ __forceinline__ float bfhi_f(uint32_t p) { return __uint_as_float(p & 0xffff0000u); }

__device__ __forceinline__ float sigmoidf_fast(float x) {
    return __fdividef(1.0f, 1.0f + __expf(-x));
}
__device__ __forceinline__ float tanhf_fast(float x) {
    return 1.0f - __fdividef(2.0f, __expf(2.0f * x) + 1.0f);
}

#define LDSM4(r0, r1, r2, r3, a)                                            \
    asm volatile("ldmatrix.sync.aligned.m8n8.x4.shared.b16 {%0,%1,%2,%3}, [%4];" \
                 : "=r"(r0), "=r"(r1), "=r"(r2), "=r"(r3) : "r"(a))

#define MMA16816(c, a0, a1, a2, a3, b0, b1)                                 \
    asm volatile("mma.sync.aligned.m16n8k16.row.col.f32.bf16.bf16.f32 "     \
                 "{%0,%1,%2,%3}, {%4,%5,%6,%7}, {%8,%9}, {%0,%1,%2,%3};"    \
                 : "+f"((c)[0]), "+f"((c)[1]), "+f"((c)[2]), "+f"((c)[3])   \
                 : "r"(a0), "r"(a1), "r"(a2), "r"(a3), "r"(b0), "r"(b1))

// ---------------------------------------------------------------------------
// Kernel 0: index dtype detection (int32 vs int64 node ids)
// ---------------------------------------------------------------------------
__global__ void detect_kernel(const unsigned long long* __restrict__ src,
                              const unsigned long long* __restrict__ dst) {
    if (threadIdx.x == 0 && blockIdx.x == 0) {
        unsigned long long acc = 0;
#pragma unroll
        for (int i = 0; i < 8; i++) acc |= (src[i] >> 32) | (dst[i] >> 32);
        g_is32 = (acc != 0ULL) ? 1 : 0;
    }
}

// ---------------------------------------------------------------------------
// Kernel 1: zero accumulator
// ---------------------------------------------------------------------------
__global__ void zero_kernel(int n4) {
    int i = blockIdx.x * blockDim.x + threadIdx.x;
    if (i < n4) g_hnew4[i] = make_float4(0.f, 0.f, 0.f, 0.f);
}

// ---------------------------------------------------------------------------
// Kernel 2: edge scatter (red.global.add.v4.f32 into L2-resident accumulator)
// ---------------------------------------------------------------------------
__global__ void scatter_kernel(const float4* __restrict__ h4,
                               const float* __restrict__ ew,
                               const void* __restrict__ srcp,
                               const void* __restrict__ dstp,
                               int E) {
    int gid = blockIdx.x * blockDim.x + threadIdx.x;
    int e = gid >> 4;
    int p = gid & 15;
    if (e >= E) return;
    int s, d;
    if (g_is32) {
        s = ((const int*)srcp)[e];
        d = ((const int*)dstp)[e];
    } else {
        s = (int)((const long long*)srcp)[e];
        d = (int)((const long long*)dstp)[e];
    }
    float w = ew[e];
    float4 v = __ldg(&h4[s * 16 + p]);
    v.x *= w; v.y *= w; v.z *= w; v.w *= w;
    unsigned long long gptr = __cvta_generic_to_global((void*)&g_hnew4[d * 16 + p]);
    asm volatile("red.global.add.v4.f32 [%0], {%1, %2, %3, %4};"
                 :: "l"(gptr), "f"(v.x), "f"(v.y), "f"(v.z), "f"(v.w) : "memory");
}

// ---------------------------------------------------------------------------
// Kernel 3: prep — bf16 hi/lo weight image + fused biases.
// B logical: [256 cols'][128 k], col' = j*4 + gate, k<64 -> x-part, k>=64 -> h-part.
//   gate 0 (r):  Wih_r | Whh_r      gate 1 (z): Wih_z | Whh_z
//   gate 2 (in): Wih_n | 0          gate 3 (hn): 0 | Whh_n
// Stored row-major with 272B row stride (16B-chunk layout: byte(k) =
// (k>>3)*16 + (k&7)*2) — the exact SMEM image CTAs memcpy.
// ---------------------------------------------------------------------------
__global__ void prep_kernel(const float* __restrict__ Wih,
                            const float* __restrict__ Whh,
                            const float* __restrict__ bih,
                            const float* __restrict__ bhh) {
    int idx = blockIdx.x * blockDim.x + threadIdx.x;   // 256 cols' x 32 quads
    if (idx < 8192) {
        int colp = idx >> 5, q = idx & 31;             // q: 4-k quad, q<16 -> x half
        int j = colp >> 2, g = colp & 3;
        int kk = (q & 15) * 4;                         // k within 64-half
        bool isX = (q < 16);
        float4 v = make_float4(0.f, 0.f, 0.f, 0.f);
        const float* srcRow = nullptr;
        if (g == 0)      srcRow = isX ? &Wih[j * 64]         : &Whh[j * 64];
        else if (g == 1) srcRow = isX ? &Wih[(64 + j) * 64]  : &Whh[(64 + j) * 64];
        else if (g == 2) srcRow = isX ? &Wih[(128 + j) * 64] : nullptr;
        else             srcRow = isX ? nullptr              : &Whh[(128 + j) * 64];
        if (srcRow) v = *(const float4*)(srcRow + kk);

        uint32_t h01 = cvtbf2(v.y, v.x), h23 = cvtbf2(v.w, v.z);
        uint32_t l01 = cvtbf2(v.y - bfhi_f(h01), v.x - bflo_f(h01));
        uint32_t l23 = cvtbf2(v.w - bfhi_f(h23), v.z - bflo_f(h23));
        uint32_t off = (uint32_t)colp * STRIDE_A + ((q >> 1) << 4) + ((q & 1) << 3);
        *(uint2*)(g_Bimg + off)          = make_uint2(h01, h23);
        *(uint2*)(g_Bimg + off + B_HALF) = make_uint2(l01, l23);
    }
    if (idx < 64) {
        g_biasf[idx * 4 + 0] = bih[idx] + bhh[idx];
        g_biasf[idx * 4 + 1] = bih[64 + idx] + bhh[64 + idx];
        g_biasf[idx * 4 + 2] = bih[128 + idx];
        g_biasf[idx * 4 + 3] = bhh[128 + idx];
    }
}

// ---------------------------------------------------------------------------
// Kernel 4: persistent bf16x3 mma.sync GEMM + fused GRU epilogue.
// CTA: 256 thr (8 warps). Warp tile: 16 m-rows x 256 n-cols. K=128.
// 3 passes: Ahi*Bhi + Ahi*Blo + Alo*Bhi into fp32 accum (128 regs/thread).
// ---------------------------------------------------------------------------
__global__ void __launch_bounds__(256, 1)
gemm_gru_kernel(const float4* __restrict__ h4, float* __restrict__ out,
                int Nn, int n_tiles) {
    extern __shared__ __align__(16) char smem[];
    const uint32_t sb = smem_u32(smem);
    const int tid = threadIdx.x;
    const int w = tid >> 5, l = tid & 31;
    const int gid = l >> 2, tg = l & 3;

    // --- B image + bias -> SMEM (linear, pre-formatted) ---
    {
        const uint4* srcB = (const uint4*)g_Bimg;
        uint4* dstB = (uint4*)(smem + SM_B);
        for (int i = tid; i < (2 * B_HALF) / 16; i += 256) dstB[i] = srcB[i];
        ((float*)smem)[tid] = g_biasf[tid];
    }
    __syncthreads();

    // ldmatrix lane address bases (272B row stride)
    const int sel = l >> 3;
    const uint32_t a_base = sb + SM_A +
        (uint32_t)((w * 16 + ((sel & 1) << 3) + (l & 7)) * STRIDE_A + ((sel >> 1) << 4));
    const uint32_t b_base = sb + SM_B +
        (uint32_t)((((sel >> 1) << 3) + (l & 7)) * STRIDE_A + ((sel & 1) << 4));

    const bool ev = !(l & 1);
    const int nodeloc = gid + (ev ? 0 : 8);

    for (int t = blockIdx.x; t < n_tiles; t += gridDim.x) {
        const int m0 = t << 7;

        // --- A tile: f32 -> bf16 hi/lo split, 272B-stride SMEM layout ---
#pragma unroll
        for (int it = 0; it < 16; it++) {
            int row = it * 8 + w;
            int node = m0 + row;
            int kq = l;                               // 4-k quad; <16: hnew, >=16: h
            float4 v = make_float4(0.f, 0.f, 0.f, 0.f);
            if (node < Nn)
                v = (kq < 16) ? g_hnew4[node * 16 + kq]
                              : __ldg(&h4[node * 16 + (kq - 16)]);
            uint32_t h01 = cvtbf2(v.y, v.x), h23 = cvtbf2(v.w, v.z);
            uint32_t l01 = cvtbf2(v.y - bfhi_f(h01), v.x - bflo_f(h01));
            uint32_t l23 = cvtbf2(v.w - bfhi_f(h23), v.z - bflo_f(h23));
            uint32_t off = (uint32_t)SM_A + (uint32_t)row * STRIDE_A +
                           ((uint32_t)(kq >> 1) << 4) + ((uint32_t)(kq & 1) << 3);
            *(uint2*)(smem + off)          = make_uint2(h01, h23);
            *(uint2*)(smem + off + A_HALF) = make_uint2(l01, l23);
        }
        __syncthreads();

        // --- GEMM: 3 split passes, 8 k-steps, 32 n-blocks ---
        float acc[128];
#pragma unroll
        for (int i = 0; i < 128; i++) acc[i] = 0.f;

#pragma unroll 1
        for (int p = 0; p < 3; p++) {
            const uint32_t ab = a_base + ((p == 2) ? (uint32_t)A_HALF : 0u);
            const uint32_t bb = b_base + ((p == 1) ? (uint32_t)B_HALF : 0u);
#pragma unroll
            for (int s = 0; s < 8; s++) {
                uint32_t a0, a1, a2, a3;
                LDSM4(a0, a1, a2, a3, ab + (uint32_t)s * 32);
#pragma unroll
                for (int nb = 0; nb < 16; nb++) {
                    uint32_t b0, b1, b2, b3;
                    LDSM4(b0, b1, b2, b3,
                          bb + (uint32_t)nb * (16 * STRIDE_A) + (uint32_t)s * 32);
                    MMA16816(&acc[(nb * 2) * 4],     a0, a1, a2, a3, b0, b1);
                    MMA16816(&acc[(nb * 2 + 1) * 4], a0, a1, a2, a3, b2, b3);
                }
            }
        }

        // --- Epilogue phase 1: gate math; output stashed into acc[fn*4] ---
        const int noderow = w * 16 + nodeloc;
        const uint32_t habase = sb + SM_A + (uint32_t)noderow * STRIDE_A;
#pragma unroll
        for (int fn = 0; fn < 32; fn++) {
            int jj = fn * 2 + (tg >> 1);
            float4 b4 = *(const float4*)(smem + SM_BIAS + jj * 16);
            float s0 = acc[fn * 4], s1 = acc[fn * 4 + 1];
            float s2 = acc[fn * 4 + 2], s3 = acc[fn * 4 + 3];
            float t0 = __shfl_xor_sync(0xffffffffu, s0, 1);
            float t1 = __shfl_xor_sync(0xffffffffu, s1, 1);
            float t2 = __shfl_xor_sync(0xffffffffu, s2, 1);
            float t3 = __shfl_xor_sync(0xffffffffu, s3, 1);
            float rs = ev ? s0 : t2;
            float zs = ev ? s1 : t3;
            float is = ev ? t0 : s2;
            float hs = ev ? t1 : s3;
            float r  = sigmoidf_fast(rs + b4.x);
            float z  = sigmoidf_fast(zs + b4.y);
            float nn = tanhf_fast(is + b4.z + r * (hs + b4.w));
            int kcol = 64 + jj;                 // h lives in A cols 64..127
            uint32_t hoff = (uint32_t)SM_A + (uint32_t)noderow * STRIDE_A +
                            ((uint32_t)(kcol >> 3) << 4) + ((uint32_t)(kcol & 7) << 1);
            uint32_t hib = *(const unsigned short*)(smem + hoff);
            uint32_t lob = *(const unsigned short*)(smem + hoff + A_HALF);
            float hv = __uint_as_float(hib << 16) + __uint_as_float(lob << 16);
            acc[fn * 4] = (1.f - z) * nn + z * hv;
        }
        __syncwarp();

        // --- Epilogue phase 2: stage into warp-local SMEM (XOR swizzle) ---
        const uint32_t stw = (uint32_t)SM_A + (uint32_t)w * (16 * STRIDE_A);
        const uint32_t pat = ((uint32_t)nodeloc & 7) << 5;
#pragma unroll
        for (int fn = 0; fn < 32; fn++) {
            int jj = fn * 2 + (tg >> 1);
            uint32_t sa = stw + (uint32_t)nodeloc * 256 + (((uint32_t)jj << 2) ^ pat);
            *(float*)(smem + sa) = acc[fn * 4];
        }
        __syncwarp();

        // --- Epilogue phase 3: coalesced 16B stores ---
#pragma unroll
        for (int it = 0; it < 8; it++) {
            int idx = it * 32 + l;
            int nl = idx >> 4, c16 = idx & 15;
            uint32_t ra = stw + (uint32_t)nl * 256 +
                          (((uint32_t)c16 << 4) ^ (((uint32_t)nl & 7) << 5));
            uint4 v = *(const uint4*)(smem + ra);
            int node = m0 + w * 16 + nl;
            if (node < Nn) *(uint4*)(out + (size_t)node * 64 + c16 * 4) = v;
        }
        __syncthreads();   // A region safe to rewrite next tile
    }
}

// ---------------------------------------------------------------------------
// Launch
// ---------------------------------------------------------------------------
extern "C" void kernel_launch(void* const* d_in, const int* in_sizes, int n_in,
                              void* d_out, int out_size) {
    const float* h   = (const float*)d_in[0];
    const float* ew  = (const float*)d_in[1];
    const float* Wih = (const float*)d_in[2];
    const float* Whh = (const float*)d_in[3];
    const float* bih = (const float*)d_in[4];
    const float* bhh = (const float*)d_in[5];
    const void* srcp = d_in[6];
    const void* dstp = d_in[7];
    float* out       = (float*)d_out;

    int E  = in_sizes[1];
    int Nn = in_sizes[0] / D;
    int n_tiles = (Nn + 127) / 128;

    detect_kernel<<<1, 32>>>((const unsigned long long*)srcp,
                             (const unsigned long long*)dstp);

    int n4 = Nn * (D / 4);
    zero_kernel<<<(n4 + 255) / 256, 256>>>(n4);

    prep_kernel<<<32, 256>>>(Wih, Whh, bih, bhh);

    long long total = (long long)E * 16;
    scatter_kernel<<<(int)((total + 255) / 256), 256>>>((const float4*)h, ew,
                                                        srcp, dstp, E);

    cudaFuncSetAttribute(gemm_gru_kernel,
                         cudaFuncAttributeMaxDynamicSharedMemorySize, SM_TOT);
    gemm_gru_kernel<<<148, 256, SM_TOT>>>((const float4*)h, out, Nn, n_tiles);
}